// round 13
// baseline (speedup 1.0000x reference)
#include <cuda_runtime.h>
#include <cuda_fp16.h>
#include <cstdint>

// ---------------------------------------------------------------------------
// Problem constants
// ---------------------------------------------------------------------------
#define IN_F   4096
#define OUT_F  4096
#define NBLKS  128      // IN_F / 32
#define MROWS  16384    // 4 * 4096 tokens

// Scratch (allocation-free rule: __device__ globals)
__device__ float  g_Q[NBLKS * 32 * 32];             // 512 KB
__device__ __half g_W2h[(size_t)OUT_F * IN_F];      // 32 MB  rotated+dequantized W, fp16
__device__ __half g_Xh[(size_t)MROWS * IN_F];       // 128 MB x in fp16

// ---------------------------------------------------------------------------
// Helpers
// ---------------------------------------------------------------------------
__device__ __forceinline__ uint32_t smem_u32(const void* p) {
    uint32_t a;
    asm("{ .reg .u64 t; cvta.to.shared.u64 t, %1; cvt.u32.u64 %0, t; }" : "=r"(a) : "l"(p));
    return a;
}

__device__ __forceinline__ void cp16(uint32_t s, const void* g) {
    asm volatile("cp.async.cg.shared.global [%0], [%1], 16;" :: "r"(s), "l"(g));
}
#define CP_COMMIT() asm volatile("cp.async.commit_group;" ::: "memory")
#define CP_WAIT(n)  asm volatile("cp.async.wait_group %0;" :: "n"(n) : "memory")

#define LDM_X4(R, addr) \
    asm volatile("ldmatrix.sync.aligned.m8n8.x4.shared.b16 {%0,%1,%2,%3}, [%4];" \
                 : "=r"((R)[0]), "=r"((R)[1]), "=r"((R)[2]), "=r"((R)[3]) : "r"(addr))

__device__ __forceinline__ void mma_f16(float c[4], const uint32_t a[4], uint32_t b0, uint32_t b1) {
    asm volatile(
        "mma.sync.aligned.m16n8k16.row.col.f32.f16.f16.f32 "
        "{%0,%1,%2,%3}, {%4,%5,%6,%7}, {%8,%9}, {%0,%1,%2,%3};"
        : "+f"(c[0]), "+f"(c[1]), "+f"(c[2]), "+f"(c[3])
        : "r"(a[0]), "r"(a[1]), "r"(a[2]), "r"(a[3]), "r"(b0), "r"(b1));
}

// ---------------------------------------------------------------------------
// Prep kernel 1: blocks [0,128): Cayley Q = (I-S)^{-1}(I+S)  (256 thr, 4 rows
// per thread, GJ no pivot — diag-dominant). Blocks [128, 128+32768): first
// half of x -> fp16 conversion (DRAM-bound, overlaps the latency-bound GJ).
// ---------------------------------------------------------------------------
#define XHALF 32768     // half of MROWS*IN_F / (256*4)

__global__ __launch_bounds__(256) void prep1_kernel(
    const float* __restrict__ x, const float* __restrict__ oft_r)
{
    __shared__ float A[32][33];
    __shared__ float Bm[32][33];
    int blk = blockIdx.x;
    if (blk >= NBLKS) {
        size_t i = ((size_t)(blk - NBLKS) * 256 + threadIdx.x) * 4;
        float4 v = *(const float4*)(x + i);
        *(__half2*)(g_Xh + i)     = __floats2half2_rn(v.x, v.y);
        *(__half2*)(g_Xh + i + 2) = __floats2half2_rn(v.z, v.w);
        return;
    }
    int n = blk;
    int tid = threadIdx.x;
    int j = tid & 31, i0 = tid >> 5;            // i0 = 0..7; rows i0+8p
    const float* R = oft_r + n * 1024;
    #pragma unroll
    for (int p = 0; p < 4; p++) {
        int i = i0 + 8 * p;
        float s  = 0.5f * (R[i * 32 + j] - R[j * 32 + i]);
        float id = (i == j) ? 1.0f : 0.0f;
        A[i][j]  = id - s;
        Bm[i][j] = id + s;
    }
    __syncthreads();
    for (int k = 0; k < 32; k++) {
        float fac[4];
        #pragma unroll
        for (int p = 0; p < 4; p++) fac[p] = A[i0 + 8 * p][k] / A[k][k];
        __syncthreads();
        #pragma unroll
        for (int p = 0; p < 4; p++) {
            int i = i0 + 8 * p;
            if (i != k) {
                A[i][j]  = fmaf(-fac[p], A[k][j],  A[i][j]);
                Bm[i][j] = fmaf(-fac[p], Bm[k][j], Bm[i][j]);
            }
        }
        __syncthreads();
    }
    #pragma unroll
    for (int p = 0; p < 4; p++) {
        int i = i0 + 8 * p;
        g_Q[n * 1024 + i * 32 + j] = Bm[i][j] / A[i][i];
    }
}

// ---------------------------------------------------------------------------
// Prep kernel 2: blocks [0, DBLKS): dequant + fold rotation (fp16 out),
// SHFL-FREE: codebook values staged per-warp in SMEM, Q row + W read as
// LDS.128 (Q padded to 36 floats/row for 16B alignment + conflict-free
// phases; Ws reads are warp-broadcast). Blocks [DBLKS, +32768): second half
// of x -> fp16.
// ---------------------------------------------------------------------------
#define DBLKS 65536     // NBLKS * OUT_F/8

__global__ __launch_bounds__(256) void prep2_kernel(
    const float* __restrict__ x, const int* __restrict__ codes,
    const float* __restrict__ codebooks, const float* __restrict__ scales)
{
    __shared__ float Qs[32][36];
    __shared__ float Ws[8][32];
    int blk = blockIdx.x;
    if (blk >= DBLKS) {
        size_t i = ((size_t)(blk - DBLKS + XHALF) * 256 + threadIdx.x) * 4;
        float4 v = *(const float4*)(x + i);
        *(__half2*)(g_Xh + i)     = __floats2half2_rn(v.x, v.y);
        *(__half2*)(g_Xh + i + 2) = __floats2half2_rn(v.z, v.w);
        return;
    }
    int n = blk & 127;
    int obase = (blk >> 7) * 8;
    int tid = threadIdx.x;
    int w = tid >> 5, lane = tid & 31;

    for (int idx = tid; idx < 1024; idx += 256)
        Qs[idx >> 5][idx & 31] = g_Q[n * 1024 + idx];
    __syncthreads();

    int o = obase + w;
    int code = codes[o * 512 + 4 * n + (lane >> 3)];
    Ws[w][lane] = codebooks[code * 8 + (lane & 7)];

    float4 q[8];
    #pragma unroll
    for (int c = 0; c < 8; c++) q[c] = *(const float4*)&Qs[lane][c * 4];
    __syncwarp();

    float acc = 0.f;
    #pragma unroll
    for (int c = 0; c < 8; c++) {
        float4 wv = *(const float4*)&Ws[w][c * 4];   // broadcast
        acc = fmaf(q[c].x, wv.x, acc);
        acc = fmaf(q[c].y, wv.y, acc);
        acc = fmaf(q[c].z, wv.z, acc);
        acc = fmaf(q[c].w, wv.w, acc);
    }
    acc *= scales[o];
    g_W2h[(size_t)o * IN_F + n * 32 + lane] = __float2half_rn(acc);
}

// ---------------------------------------------------------------------------
// Kernel 3: fp16 mma.sync GEMM — EXACT R9 config (proven 1339us):
// CTA 128x256, 256 threads (8 warps 2x4), warp tile 64x64, KBLK=64
// (4 k16 substeps/stage), 3-stage cp.async (144 KB), register fragment
// double-buffering, 128B-row j^(row&7) swizzle, CP_WAIT(1).
// RF: ~225 regs x 256 thr = 58K < 64K (standing check).
// ---------------------------------------------------------------------------
#define STAGES 3
#define KBLK   64
#define TM     128
#define TN     256
#define KITERS (IN_F / KBLK)            // 64
#define A_BYTES (TM * KBLK * 2)         // 16 KB
#define B_BYTES (TN * KBLK * 2)         // 32 KB
#define STAGE_BYTES (A_BYTES + B_BYTES) // 48 KB

__device__ __forceinline__ uint32_t swz(int row, int j) {
    return (uint32_t)(row * 128 + ((j ^ (row & 7)) << 4));
}

__device__ __forceinline__ void stage_fill(uint32_t sb,
        const __half* gA, const __half* gB, uint32_t so0, int kb)
{
    #pragma unroll
    for (int p = 0; p < 4; p++)
        cp16(sb + so0 + p * 4096,           gA + (size_t)p * 32 * IN_F + kb);
    #pragma unroll
    for (int p = 0; p < 8; p++)
        cp16(sb + A_BYTES + so0 + p * 4096, gB + (size_t)p * 32 * IN_F + kb);
}

__device__ __forceinline__ void frag_load(uint32_t a[4][4], uint32_t b[4][4],
                                          uint32_t sb, uint32_t aoff, uint32_t boff)
{
    #pragma unroll
    for (int mi = 0; mi < 4; mi++) LDM_X4(a[mi], sb + aoff + mi * 2048);
    #pragma unroll
    for (int p = 0; p < 4; p++)    LDM_X4(b[p], sb + A_BYTES + boff + p * 2048);
}

__device__ __forceinline__ void mma_block(float acc[4][8][4],
                                          const uint32_t a[4][4], const uint32_t b[4][4])
{
    #pragma unroll
    for (int mi = 0; mi < 4; mi++)
        #pragma unroll
        for (int p = 0; p < 4; p++) {
            mma_f16(acc[mi][2 * p],     a[mi], b[p][0], b[p][2]);
            mma_f16(acc[mi][2 * p + 1], a[mi], b[p][1], b[p][3]);
        }
}

__global__ __launch_bounds__(256, 1)
void gemm_kernel(const float* __restrict__ bias, float* __restrict__ out)
{
    extern __shared__ char smem[];
    uint32_t sbase = smem_u32(smem);
    uint32_t buf_lim = sbase + 2 * STAGE_BYTES;

    int tid  = threadIdx.x;
    int wid  = tid >> 5, lane = tid & 31;
    int g    = lane >> 2, tig = lane & 3;
    int lr   = lane & 7;
    int q    = lane >> 3;
    int wm   = (wid >> 2) * 64;
    int wn   = (wid & 3) * 64;
    int nbase = blockIdx.x * TN;
    int mbase = blockIdx.y * TM;

    int ra = wm + lr + ((q & 1) << 3);
    int rb = wn + lr + ((q & 1) << 3);
    int ja = q >> 1;
    uint32_t aoff[4], boff[4];
    #pragma unroll
    for (int s = 0; s < 4; s++) {
        aoff[s] = swz(ra, 2 * s + ja);
        boff[s] = swz(rb, 2 * s + ja);
    }

    int r0 = tid >> 3, j0 = tid & 7;
    const __half* gA = g_Xh  + (size_t)(mbase + r0) * IN_F + j0 * 8;
    const __half* gB = g_W2h + (size_t)(nbase + r0) * IN_F + j0 * 8;
    uint32_t so0 = swz(r0, j0);

    float acc[4][8][4];
    #pragma unroll
    for (int mi = 0; mi < 4; mi++)
        #pragma unroll
        for (int ni = 0; ni < 8; ni++)
            #pragma unroll
            for (int p = 0; p < 4; p++) acc[mi][ni][p] = 0.f;

    // Prologue: fill stages 0,1
    stage_fill(sbase,               gA, gB, so0, 0);
    CP_COMMIT();
    stage_fill(sbase + STAGE_BYTES, gA, gB, so0, KBLK);
    CP_COMMIT();
    CP_WAIT(1);
    __syncthreads();

    uint32_t fa[2][4][4], fb[2][4][4];
    frag_load(fa[0], fb[0], sbase, aoff[0], boff[0]);

    uint32_t sb_read = sbase;
    uint32_t sb_fill = buf_lim;

    for (int k = 0; k < KITERS; k++) {
        if (k + 2 < KITERS)
            stage_fill(sb_fill, gA, gB, so0, (k + 2) * KBLK);
        CP_COMMIT();

        #pragma unroll
        for (int s = 0; s < 4; s++) {
            if (s < 3) {
                frag_load(fa[(s + 1) & 1], fb[(s + 1) & 1], sb_read, aoff[s + 1], boff[s + 1]);
            } else {
                CP_WAIT(1);
                __syncthreads();
                if (k + 1 < KITERS) {
                    uint32_t nxt = (sb_read == buf_lim) ? sbase : sb_read + STAGE_BYTES;
                    frag_load(fa[0], fb[0], nxt, aoff[0], boff[0]);
                }
            }
            mma_block(acc, fa[s & 1], fb[s & 1]);
        }

        sb_read = (sb_read == buf_lim) ? sbase : sb_read + STAGE_BYTES;
        sb_fill = (sb_fill == buf_lim) ? sbase : sb_fill + STAGE_BYTES;
    }

    // Epilogue: direct store + bias
    #pragma unroll
    for (int mi = 0; mi < 4; mi++) {
        int r = mbase + wm + mi * 16 + g;
        #pragma unroll
        for (int ni = 0; ni < 8; ni++) {
            int col = nbase + wn + ni * 8 + tig * 2;
            float2 bv = *(const float2*)(bias + col);
            float2 v0 = make_float2(acc[mi][ni][0] + bv.x, acc[mi][ni][1] + bv.y);
            float2 v1 = make_float2(acc[mi][ni][2] + bv.x, acc[mi][ni][3] + bv.y);
            *(float2*)(out + (size_t)r * OUT_F + col)       = v0;
            *(float2*)(out + (size_t)(r + 8) * OUT_F + col) = v1;
        }
    }
}

// ---------------------------------------------------------------------------
// Launch
// ---------------------------------------------------------------------------
extern "C" void kernel_launch(void* const* d_in, const int* in_sizes, int n_in,
                              void* d_out, int out_size)
{
    const float* x         = (const float*)d_in[0];
    const float* oft_r     = (const float*)d_in[1];
    const int*   codes     = (const int*)d_in[2];
    const float* codebooks = (const float*)d_in[3];
    const float* scales    = (const float*)d_in[4];
    const float* bias      = (const float*)d_in[5];
    float*       out       = (float*)d_out;

    prep1_kernel<<<NBLKS + XHALF, 256>>>(x, oft_r);
    prep2_kernel<<<DBLKS + XHALF, 256>>>(x, codes, codebooks, scales);

    int smem_bytes = STAGES * STAGE_BYTES;   // 144 KB
    cudaFuncSetAttribute(gemm_kernel, cudaFuncAttributeMaxDynamicSharedMemorySize, smem_bytes);
    gemm_kernel<<<dim3(OUT_F / TN, MROWS / TM), 256, smem_bytes>>>(bias, out);
}

// round 14
// speedup vs baseline: 1.0241x; 1.0241x over previous
#include <cuda_runtime.h>
#include <cuda_fp16.h>
#include <cstdint>

// ---------------------------------------------------------------------------
// Problem constants
// ---------------------------------------------------------------------------
#define IN_F   4096
#define OUT_F  4096
#define NBLKS  128      // IN_F / 32
#define MROWS  16384    // 4 * 4096 tokens

// Scratch (allocation-free rule: __device__ globals)
__device__ float  g_Q[NBLKS * 32 * 32];             // 512 KB
__device__ __half g_W2h[(size_t)OUT_F * IN_F];      // 32 MB  rotated+dequantized W, fp16
__device__ __half g_Xh[(size_t)MROWS * IN_F];       // 128 MB x in fp16

// ---------------------------------------------------------------------------
// Helpers
// ---------------------------------------------------------------------------
__device__ __forceinline__ uint32_t smem_u32(const void* p) {
    uint32_t a;
    asm("{ .reg .u64 t; cvta.to.shared.u64 t, %1; cvt.u32.u64 %0, t; }" : "=r"(a) : "l"(p));
    return a;
}

__device__ __forceinline__ void cp16(uint32_t s, const void* g) {
    asm volatile("cp.async.cg.shared.global [%0], [%1], 16;" :: "r"(s), "l"(g));
}
#define CP_COMMIT() asm volatile("cp.async.commit_group;" ::: "memory")
#define CP_WAIT(n)  asm volatile("cp.async.wait_group %0;" :: "n"(n) : "memory")

#define LDM_X4(R, addr) \
    asm volatile("ldmatrix.sync.aligned.m8n8.x4.shared.b16 {%0,%1,%2,%3}, [%4];" \
                 : "=r"((R)[0]), "=r"((R)[1]), "=r"((R)[2]), "=r"((R)[3]) : "r"(addr))

__device__ __forceinline__ void mma_f16(float c[4], const uint32_t a[4], uint32_t b0, uint32_t b1) {
    asm volatile(
        "mma.sync.aligned.m16n8k16.row.col.f32.f16.f16.f32 "
        "{%0,%1,%2,%3}, {%4,%5,%6,%7}, {%8,%9}, {%0,%1,%2,%3};"
        : "+f"(c[0]), "+f"(c[1]), "+f"(c[2]), "+f"(c[3])
        : "r"(a[0]), "r"(a[1]), "r"(a[2]), "r"(a[3]), "r"(b0), "r"(b1));
}

// ---------------------------------------------------------------------------
// Kernel 1: Cayley  Q = (I-S)^{-1}(I+S)   (Gauss-Jordan, diag-dominant, no pivot)
// ---------------------------------------------------------------------------
__global__ void cayley_kernel(const float* __restrict__ oft_r) {
    __shared__ float A[32][33];
    __shared__ float Bm[32][33];
    int n = blockIdx.x;
    int j = threadIdx.x, i = threadIdx.y;
    const float* R = oft_r + n * 1024;
    float s  = 0.5f * (R[i * 32 + j] - R[j * 32 + i]);
    float id = (i == j) ? 1.0f : 0.0f;
    A[i][j]  = id - s;
    Bm[i][j] = id + s;
    __syncthreads();
    for (int k = 0; k < 32; k++) {
        float fac = A[i][k] / A[k][k];
        __syncthreads();
        if (i != k) {
            A[i][j]  = fmaf(-fac, A[k][j],  A[i][j]);
            Bm[i][j] = fmaf(-fac, Bm[k][j], Bm[i][j]);
        }
        __syncthreads();
    }
    g_Q[n * 1024 + i * 32 + j] = Bm[i][j] / A[i][i];
}

// ---------------------------------------------------------------------------
// Kernel 2 (fused prep, EXACT R9): blocks [0, XBLKS) convert x -> fp16;
// blocks [XBLKS, XBLKS+65536) dequant + fold rotation into W (fp16 out).
// ---------------------------------------------------------------------------
#define XBLKS 65536     // MROWS*IN_F / (256*4)

__global__ __launch_bounds__(256) void prep_kernel(
    const float* __restrict__ x, const int* __restrict__ codes,
    const float* __restrict__ codebooks, const float* __restrict__ scales)
{
    __shared__ float Qs[32][33];
    int blk = blockIdx.x;
    if (blk < XBLKS) {
        size_t i = ((size_t)blk * 256 + threadIdx.x) * 4;
        float4 v = *(const float4*)(x + i);
        *(__half2*)(g_Xh + i)     = __floats2half2_rn(v.x, v.y);
        *(__half2*)(g_Xh + i + 2) = __floats2half2_rn(v.z, v.w);
        return;
    }
    blk -= XBLKS;
    int n = blk & 127;                 // 0..127
    int obase = (blk >> 7) * 8;
    int tid = threadIdx.x;
    int w = tid >> 5, lane = tid & 31;

    for (int idx = tid; idx < 1024; idx += 256)
        Qs[idx >> 5][idx & 31] = g_Q[n * 1024 + idx];
    __syncthreads();

    int o = obase + w;
    int grp = 4 * n + (lane >> 3);
    int code = codes[o * 512 + grp];
    float wv = codebooks[code * 8 + (lane & 7)];

    float acc = 0.f;
    #pragma unroll
    for (int kk = 0; kk < 32; kk++) {
        float wk = __shfl_sync(0xFFFFFFFFu, wv, kk);
        acc = fmaf(Qs[lane][kk], wk, acc);
    }
    acc *= scales[o];
    g_W2h[(size_t)o * IN_F + n * 32 + lane] = __float2half_rn(acc);
}

// ---------------------------------------------------------------------------
// Kernel 3: fp16 mma.sync GEMM — R9 config (proven 1339us): CTA 128x256,
// 256 threads (8 warps 2x4), warp tile 64x64, KBLK=64, 3-stage cp.async
// (144 KB), register fragment double-buffering, 128B-row j^(row&7) swizzle,
// CP_WAIT(1). THIS ROUND'S ONE CHANGE: the 12 cp.asyncs per k-iter are split
// into 4 groups of 3 (1A+2B), one issued per MMA substep, smoothing the
// LSU/MIO burst that collided with ldmatrix issue at the k-iter top. All 12
// still precede the single CP_COMMIT at substep 3 (group semantics = R9).
// RF: ~225 regs x 256 thr = 58K < 64K (standing check).
// ---------------------------------------------------------------------------
#define STAGES 3
#define KBLK   64
#define TM     128
#define TN     256
#define KITERS (IN_F / KBLK)            // 64
#define A_BYTES (TM * KBLK * 2)         // 16 KB
#define B_BYTES (TN * KBLK * 2)         // 32 KB
#define STAGE_BYTES (A_BYTES + B_BYTES) // 48 KB

__device__ __forceinline__ uint32_t swz(int row, int j) {
    return (uint32_t)(row * 128 + ((j ^ (row & 7)) << 4));
}

// Quarter-fill: part p = 1 A-chunk + 2 B-chunks (rows r0+32p / r0+32*(2p,2p+1)).
__device__ __forceinline__ void fill_part(uint32_t sb,
        const __half* gA, const __half* gB, uint32_t so0, int kb, int p)
{
    cp16(sb + so0 + p * 4096,                     gA + (size_t)p * 32 * IN_F + kb);
    cp16(sb + A_BYTES + so0 + (2 * p) * 4096,     gB + (size_t)(2 * p) * 32 * IN_F + kb);
    cp16(sb + A_BYTES + so0 + (2 * p + 1) * 4096, gB + (size_t)(2 * p + 1) * 32 * IN_F + kb);
}

__device__ __forceinline__ void stage_fill(uint32_t sb,
        const __half* gA, const __half* gB, uint32_t so0, int kb)
{
    #pragma unroll
    for (int p = 0; p < 4; p++) fill_part(sb, gA, gB, so0, kb, p);
}

__device__ __forceinline__ void frag_load(uint32_t a[4][4], uint32_t b[4][4],
                                          uint32_t sb, uint32_t aoff, uint32_t boff)
{
    #pragma unroll
    for (int mi = 0; mi < 4; mi++) LDM_X4(a[mi], sb + aoff + mi * 2048);
    #pragma unroll
    for (int p = 0; p < 4; p++)    LDM_X4(b[p], sb + A_BYTES + boff + p * 2048);
}

__device__ __forceinline__ void mma_block(float acc[4][8][4],
                                          const uint32_t a[4][4], const uint32_t b[4][4])
{
    #pragma unroll
    for (int mi = 0; mi < 4; mi++)
        #pragma unroll
        for (int p = 0; p < 4; p++) {
            mma_f16(acc[mi][2 * p],     a[mi], b[p][0], b[p][2]);
            mma_f16(acc[mi][2 * p + 1], a[mi], b[p][1], b[p][3]);
        }
}

__global__ __launch_bounds__(256, 1)
void gemm_kernel(const float* __restrict__ bias, float* __restrict__ out)
{
    extern __shared__ char smem[];
    uint32_t sbase = smem_u32(smem);
    uint32_t buf_lim = sbase + 2 * STAGE_BYTES;

    int tid  = threadIdx.x;
    int wid  = tid >> 5, lane = tid & 31;
    int g    = lane >> 2, tig = lane & 3;
    int lr   = lane & 7;
    int q    = lane >> 3;
    int wm   = (wid >> 2) * 64;
    int wn   = (wid & 3) * 64;
    int nbase = blockIdx.x * TN;
    int mbase = blockIdx.y * TM;

    int ra = wm + lr + ((q & 1) << 3);
    int rb = wn + lr + ((q & 1) << 3);
    int ja = q >> 1;
    uint32_t aoff[4], boff[4];
    #pragma unroll
    for (int s = 0; s < 4; s++) {
        aoff[s] = swz(ra, 2 * s + ja);
        boff[s] = swz(rb, 2 * s + ja);
    }

    int r0 = tid >> 3, j0 = tid & 7;
    const __half* gA = g_Xh  + (size_t)(mbase + r0) * IN_F + j0 * 8;
    const __half* gB = g_W2h + (size_t)(nbase + r0) * IN_F + j0 * 8;
    uint32_t so0 = swz(r0, j0);

    float acc[4][8][4];
    #pragma unroll
    for (int mi = 0; mi < 4; mi++)
        #pragma unroll
        for (int ni = 0; ni < 8; ni++)
            #pragma unroll
            for (int p = 0; p < 4; p++) acc[mi][ni][p] = 0.f;

    // Prologue: fill stages 0,1
    stage_fill(sbase,               gA, gB, so0, 0);
    CP_COMMIT();
    stage_fill(sbase + STAGE_BYTES, gA, gB, so0, KBLK);
    CP_COMMIT();
    CP_WAIT(1);
    __syncthreads();

    uint32_t fa[2][4][4], fb[2][4][4];
    frag_load(fa[0], fb[0], sbase, aoff[0], boff[0]);

    uint32_t sb_read = sbase;
    uint32_t sb_fill = buf_lim;

    for (int k = 0; k < KITERS; k++) {
        bool do_fill = (k + 2 < KITERS);

        #pragma unroll
        for (int s = 0; s < 4; s++) {
            if (do_fill)
                fill_part(sb_fill, gA, gB, so0, (k + 2) * KBLK, s);
            if (s < 3) {
                frag_load(fa[(s + 1) & 1], fb[(s + 1) & 1], sb_read, aoff[s + 1], boff[s + 1]);
            } else {
                CP_COMMIT();                 // single group per k-iter (after all 12)
                CP_WAIT(1);                  // stage k+1 landed
                __syncthreads();
                if (k + 1 < KITERS) {
                    uint32_t nxt = (sb_read == buf_lim) ? sbase : sb_read + STAGE_BYTES;
                    frag_load(fa[0], fb[0], nxt, aoff[0], boff[0]);
                }
            }
            mma_block(acc, fa[s & 1], fb[s & 1]);
        }

        sb_read = (sb_read == buf_lim) ? sbase : sb_read + STAGE_BYTES;
        sb_fill = (sb_fill == buf_lim) ? sbase : sb_fill + STAGE_BYTES;
    }

    // Epilogue: direct store + bias
    #pragma unroll
    for (int mi = 0; mi < 4; mi++) {
        int r = mbase + wm + mi * 16 + g;
        #pragma unroll
        for (int ni = 0; ni < 8; ni++) {
            int col = nbase + wn + ni * 8 + tig * 2;
            float2 bv = *(const float2*)(bias + col);
            float2 v0 = make_float2(acc[mi][ni][0] + bv.x, acc[mi][ni][1] + bv.y);
            float2 v1 = make_float2(acc[mi][ni][2] + bv.x, acc[mi][ni][3] + bv.y);
            *(float2*)(out + (size_t)r * OUT_F + col)       = v0;
            *(float2*)(out + (size_t)(r + 8) * OUT_F + col) = v1;
        }
    }
}

// ---------------------------------------------------------------------------
// Launch
// ---------------------------------------------------------------------------
extern "C" void kernel_launch(void* const* d_in, const int* in_sizes, int n_in,
                              void* d_out, int out_size)
{
    const float* x         = (const float*)d_in[0];
    const float* oft_r     = (const float*)d_in[1];
    const int*   codes     = (const int*)d_in[2];
    const float* codebooks = (const float*)d_in[3];
    const float* scales    = (const float*)d_in[4];
    const float* bias      = (const float*)d_in[5];
    float*       out       = (float*)d_out;

    cayley_kernel<<<NBLKS, dim3(32, 32)>>>(oft_r);
    prep_kernel<<<XBLKS + NBLKS * (OUT_F / 8), 256>>>(x, codes, codebooks, scales);

    int smem_bytes = STAGES * STAGE_BYTES;   // 144 KB
    cudaFuncSetAttribute(gemm_kernel, cudaFuncAttributeMaxDynamicSharedMemorySize, smem_bytes);
    gemm_kernel<<<dim3(OUT_F / TN, MROWS / TM), 256, smem_bytes>>>(bias, out);
}

// round 15
// speedup vs baseline: 1.0299x; 1.0057x over previous
#include <cuda_runtime.h>
#include <cuda_fp16.h>
#include <cstdint>

// ---------------------------------------------------------------------------
// Problem constants
// ---------------------------------------------------------------------------
#define IN_F   4096
#define OUT_F  4096
#define NBLKS  128      // IN_F / 32
#define MROWS  16384    // 4 * 4096 tokens

// Scratch (allocation-free rule: __device__ globals)
__device__ float  g_Q[NBLKS * 32 * 32];             // 512 KB
__device__ __half g_W2h[(size_t)OUT_F * IN_F];      // 32 MB  rotated+dequantized W, fp16
__device__ __half g_Xh[(size_t)MROWS * IN_F];       // 128 MB x in fp16

// ---------------------------------------------------------------------------
// Helpers
// ---------------------------------------------------------------------------
__device__ __forceinline__ uint32_t smem_u32(const void* p) {
    uint32_t a;
    asm("{ .reg .u64 t; cvta.to.shared.u64 t, %1; cvt.u32.u64 %0, t; }" : "=r"(a) : "l"(p));
    return a;
}

__device__ __forceinline__ void cp16(uint32_t s, const void* g) {
    asm volatile("cp.async.cg.shared.global [%0], [%1], 16;" :: "r"(s), "l"(g));
}
#define CP_COMMIT() asm volatile("cp.async.commit_group;" ::: "memory")
#define CP_WAIT(n)  asm volatile("cp.async.wait_group %0;" :: "n"(n) : "memory")

#define LDM_X4(R, addr) \
    asm volatile("ldmatrix.sync.aligned.m8n8.x4.shared.b16 {%0,%1,%2,%3}, [%4];" \
                 : "=r"((R)[0]), "=r"((R)[1]), "=r"((R)[2]), "=r"((R)[3]) : "r"(addr))

__device__ __forceinline__ void mma_f16(float c[4], const uint32_t a[4], uint32_t b0, uint32_t b1) {
    asm volatile(
        "mma.sync.aligned.m16n8k16.row.col.f32.f16.f16.f32 "
        "{%0,%1,%2,%3}, {%4,%5,%6,%7}, {%8,%9}, {%0,%1,%2,%3};"
        : "+f"(c[0]), "+f"(c[1]), "+f"(c[2]), "+f"(c[3])
        : "r"(a[0]), "r"(a[1]), "r"(a[2]), "r"(a[3]), "r"(b0), "r"(b1));
}

// ---------------------------------------------------------------------------
// Prep kernel 1: blocks [0,128): Cayley Q = (I-S)^{-1}(I+S) (256 thr, 4 rows
// per thread, GJ no pivot — validated bit-identical in R13, measured 33us
// for the whole kernel). Blocks [128, 128+32768): first half of x -> fp16
// (DRAM-bound, overlaps the latency-bound GJ).
// ---------------------------------------------------------------------------
#define XHALF 32768     // half of MROWS*IN_F / (256*4)

__global__ __launch_bounds__(256) void prep1_kernel(
    const float* __restrict__ x, const float* __restrict__ oft_r)
{
    __shared__ float A[32][33];
    __shared__ float Bm[32][33];
    int blk = blockIdx.x;
    if (blk >= NBLKS) {
        size_t i = ((size_t)(blk - NBLKS) * 256 + threadIdx.x) * 4;
        float4 v = *(const float4*)(x + i);
        *(__half2*)(g_Xh + i)     = __floats2half2_rn(v.x, v.y);
        *(__half2*)(g_Xh + i + 2) = __floats2half2_rn(v.z, v.w);
        return;
    }
    int n = blk;
    int tid = threadIdx.x;
    int j = tid & 31, i0 = tid >> 5;            // rows i0 + 8p
    const float* R = oft_r + n * 1024;
    #pragma unroll
    for (int p = 0; p < 4; p++) {
        int i = i0 + 8 * p;
        float s  = 0.5f * (R[i * 32 + j] - R[j * 32 + i]);
        float id = (i == j) ? 1.0f : 0.0f;
        A[i][j]  = id - s;
        Bm[i][j] = id + s;
    }
    __syncthreads();
    for (int k = 0; k < 32; k++) {
        float fac[4];
        #pragma unroll
        for (int p = 0; p < 4; p++) fac[p] = A[i0 + 8 * p][k] / A[k][k];
        __syncthreads();
        #pragma unroll
        for (int p = 0; p < 4; p++) {
            int i = i0 + 8 * p;
            if (i != k) {
                A[i][j]  = fmaf(-fac[p], A[k][j],  A[i][j]);
                Bm[i][j] = fmaf(-fac[p], Bm[k][j], Bm[i][j]);
            }
        }
        __syncthreads();
    }
    #pragma unroll
    for (int p = 0; p < 4; p++) {
        int i = i0 + 8 * p;
        g_Q[n * 1024 + i * 32 + j] = Bm[i][j] / A[i][i];
    }
}

// ---------------------------------------------------------------------------
// Prep kernel 2: blocks [0, DBLKS): the PROVEN R9 shfl dequant (fold rotation
// into W, fp16 out) — scheduled first so its latency-bound warps seed the
// SMs. Blocks [DBLKS, +32768): second half of x -> fp16 streams behind.
// ---------------------------------------------------------------------------
#define DBLKS 65536     // NBLKS * OUT_F/8

__global__ __launch_bounds__(256) void prep2_kernel(
    const float* __restrict__ x, const int* __restrict__ codes,
    const float* __restrict__ codebooks, const float* __restrict__ scales)
{
    __shared__ float Qs[32][33];
    int blk = blockIdx.x;
    if (blk >= DBLKS) {
        size_t i = ((size_t)(blk - DBLKS + XHALF) * 256 + threadIdx.x) * 4;
        float4 v = *(const float4*)(x + i);
        *(__half2*)(g_Xh + i)     = __floats2half2_rn(v.x, v.y);
        *(__half2*)(g_Xh + i + 2) = __floats2half2_rn(v.z, v.w);
        return;
    }
    int n = blk & 127;
    int obase = (blk >> 7) * 8;
    int tid = threadIdx.x;
    int w = tid >> 5, lane = tid & 31;

    for (int idx = tid; idx < 1024; idx += 256)
        Qs[idx >> 5][idx & 31] = g_Q[n * 1024 + idx];
    __syncthreads();

    int o = obase + w;
    int grp = 4 * n + (lane >> 3);
    int code = codes[o * 512 + grp];
    float wv = codebooks[code * 8 + (lane & 7)];

    float acc = 0.f;
    #pragma unroll
    for (int kk = 0; kk < 32; kk++) {
        float wk = __shfl_sync(0xFFFFFFFFu, wv, kk);
        acc = fmaf(Qs[lane][kk], wk, acc);
    }
    acc *= scales[o];
    g_W2h[(size_t)o * IN_F + n * 32 + lane] = __float2half_rn(acc);
}

// ---------------------------------------------------------------------------
// Kernel 3: fp16 mma.sync GEMM — EXACT R14 config (proven 1326.8us):
// CTA 128x256, 256 threads (8 warps 2x4), warp tile 64x64, KBLK=64, 3-stage
// cp.async (144 KB), register fragment double-buffering, 128B-row j^(row&7)
// swizzle, CP_WAIT(1), fill smeared as 4x(1A+2B) across the MMA substeps.
// RF: ~225 regs x 256 thr = 58K < 64K (standing check).
// ---------------------------------------------------------------------------
#define STAGES 3
#define KBLK   64
#define TM     128
#define TN     256
#define KITERS (IN_F / KBLK)            // 64
#define A_BYTES (TM * KBLK * 2)         // 16 KB
#define B_BYTES (TN * KBLK * 2)         // 32 KB
#define STAGE_BYTES (A_BYTES + B_BYTES) // 48 KB

__device__ __forceinline__ uint32_t swz(int row, int j) {
    return (uint32_t)(row * 128 + ((j ^ (row & 7)) << 4));
}

// Quarter-fill: part p = 1 A-chunk + 2 B-chunks.
__device__ __forceinline__ void fill_part(uint32_t sb,
        const __half* gA, const __half* gB, uint32_t so0, int kb, int p)
{
    cp16(sb + so0 + p * 4096,                     gA + (size_t)p * 32 * IN_F + kb);
    cp16(sb + A_BYTES + so0 + (2 * p) * 4096,     gB + (size_t)(2 * p) * 32 * IN_F + kb);
    cp16(sb + A_BYTES + so0 + (2 * p + 1) * 4096, gB + (size_t)(2 * p + 1) * 32 * IN_F + kb);
}

__device__ __forceinline__ void stage_fill(uint32_t sb,
        const __half* gA, const __half* gB, uint32_t so0, int kb)
{
    #pragma unroll
    for (int p = 0; p < 4; p++) fill_part(sb, gA, gB, so0, kb, p);
}

__device__ __forceinline__ void frag_load(uint32_t a[4][4], uint32_t b[4][4],
                                          uint32_t sb, uint32_t aoff, uint32_t boff)
{
    #pragma unroll
    for (int mi = 0; mi < 4; mi++) LDM_X4(a[mi], sb + aoff + mi * 2048);
    #pragma unroll
    for (int p = 0; p < 4; p++)    LDM_X4(b[p], sb + A_BYTES + boff + p * 2048);
}

__device__ __forceinline__ void mma_block(float acc[4][8][4],
                                          const uint32_t a[4][4], const uint32_t b[4][4])
{
    #pragma unroll
    for (int mi = 0; mi < 4; mi++)
        #pragma unroll
        for (int p = 0; p < 4; p++) {
            mma_f16(acc[mi][2 * p],     a[mi], b[p][0], b[p][2]);
            mma_f16(acc[mi][2 * p + 1], a[mi], b[p][1], b[p][3]);
        }
}

__global__ __launch_bounds__(256, 1)
void gemm_kernel(const float* __restrict__ bias, float* __restrict__ out)
{
    extern __shared__ char smem[];
    uint32_t sbase = smem_u32(smem);
    uint32_t buf_lim = sbase + 2 * STAGE_BYTES;

    int tid  = threadIdx.x;
    int wid  = tid >> 5, lane = tid & 31;
    int g    = lane >> 2, tig = lane & 3;
    int lr   = lane & 7;
    int q    = lane >> 3;
    int wm   = (wid >> 2) * 64;
    int wn   = (wid & 3) * 64;
    int nbase = blockIdx.x * TN;
    int mbase = blockIdx.y * TM;

    int ra = wm + lr + ((q & 1) << 3);
    int rb = wn + lr + ((q & 1) << 3);
    int ja = q >> 1;
    uint32_t aoff[4], boff[4];
    #pragma unroll
    for (int s = 0; s < 4; s++) {
        aoff[s] = swz(ra, 2 * s + ja);
        boff[s] = swz(rb, 2 * s + ja);
    }

    int r0 = tid >> 3, j0 = tid & 7;
    const __half* gA = g_Xh  + (size_t)(mbase + r0) * IN_F + j0 * 8;
    const __half* gB = g_W2h + (size_t)(nbase + r0) * IN_F + j0 * 8;
    uint32_t so0 = swz(r0, j0);

    float acc[4][8][4];
    #pragma unroll
    for (int mi = 0; mi < 4; mi++)
        #pragma unroll
        for (int ni = 0; ni < 8; ni++)
            #pragma unroll
            for (int p = 0; p < 4; p++) acc[mi][ni][p] = 0.f;

    // Prologue: fill stages 0,1
    stage_fill(sbase,               gA, gB, so0, 0);
    CP_COMMIT();
    stage_fill(sbase + STAGE_BYTES, gA, gB, so0, KBLK);
    CP_COMMIT();
    CP_WAIT(1);
    __syncthreads();

    uint32_t fa[2][4][4], fb[2][4][4];
    frag_load(fa[0], fb[0], sbase, aoff[0], boff[0]);

    uint32_t sb_read = sbase;
    uint32_t sb_fill = buf_lim;

    for (int k = 0; k < KITERS; k++) {
        bool do_fill = (k + 2 < KITERS);

        #pragma unroll
        for (int s = 0; s < 4; s++) {
            if (do_fill)
                fill_part(sb_fill, gA, gB, so0, (k + 2) * KBLK, s);
            if (s < 3) {
                frag_load(fa[(s + 1) & 1], fb[(s + 1) & 1], sb_read, aoff[s + 1], boff[s + 1]);
            } else {
                CP_COMMIT();                 // single group per k-iter (after all 12)
                CP_WAIT(1);                  // stage k+1 landed
                __syncthreads();
                if (k + 1 < KITERS) {
                    uint32_t nxt = (sb_read == buf_lim) ? sbase : sb_read + STAGE_BYTES;
                    frag_load(fa[0], fb[0], nxt, aoff[0], boff[0]);
                }
            }
            mma_block(acc, fa[s & 1], fb[s & 1]);
        }

        sb_read = (sb_read == buf_lim) ? sbase : sb_read + STAGE_BYTES;
        sb_fill = (sb_fill == buf_lim) ? sbase : sb_fill + STAGE_BYTES;
    }

    // Epilogue: direct store + bias
    #pragma unroll
    for (int mi = 0; mi < 4; mi++) {
        int r = mbase + wm + mi * 16 + g;
        #pragma unroll
        for (int ni = 0; ni < 8; ni++) {
            int col = nbase + wn + ni * 8 + tig * 2;
            float2 bv = *(const float2*)(bias + col);
            float2 v0 = make_float2(acc[mi][ni][0] + bv.x, acc[mi][ni][1] + bv.y);
            float2 v1 = make_float2(acc[mi][ni][2] + bv.x, acc[mi][ni][3] + bv.y);
            *(float2*)(out + (size_t)r * OUT_F + col)       = v0;
            *(float2*)(out + (size_t)(r + 8) * OUT_F + col) = v1;
        }
    }
}

// ---------------------------------------------------------------------------
// Launch
// ---------------------------------------------------------------------------
extern "C" void kernel_launch(void* const* d_in, const int* in_sizes, int n_in,
                              void* d_out, int out_size)
{
    const float* x         = (const float*)d_in[0];
    const float* oft_r     = (const float*)d_in[1];
    const int*   codes     = (const int*)d_in[2];
    const float* codebooks = (const float*)d_in[3];
    const float* scales    = (const float*)d_in[4];
    const float* bias      = (const float*)d_in[5];
    float*       out       = (float*)d_out;

    prep1_kernel<<<NBLKS + XHALF, 256>>>(x, oft_r);
    prep2_kernel<<<DBLKS + XHALF, 256>>>(x, codes, codebooks, scales);

    int smem_bytes = STAGES * STAGE_BYTES;   // 144 KB
    cudaFuncSetAttribute(gemm_kernel, cudaFuncAttributeMaxDynamicSharedMemorySize, smem_bytes);
    gemm_kernel<<<dim3(OUT_F / TN, MROWS / TM), 256, smem_bytes>>>(bias, out);
}

// round 16
// speedup vs baseline: 1.0850x; 1.0535x over previous
#include <cuda_runtime.h>
#include <cuda_fp16.h>
#include <cstdint>

// ---------------------------------------------------------------------------
// Problem constants
// ---------------------------------------------------------------------------
#define IN_F   4096
#define OUT_F  4096
#define NBLKS  128      // IN_F / 32
#define MROWS  16384    // 4 * 4096 tokens

// Scratch (allocation-free rule: __device__ globals)
__device__ float  g_Q[NBLKS * 32 * 32];             // 512 KB
__device__ __half g_W2h[(size_t)OUT_F * IN_F];      // 32 MB  rotated+dequantized W, fp16
__device__ __half g_Xh[(size_t)MROWS * IN_F];       // 128 MB x in fp16

// ---------------------------------------------------------------------------
// Helpers
// ---------------------------------------------------------------------------
__device__ __forceinline__ uint32_t smem_u32(const void* p) {
    uint32_t a;
    asm("{ .reg .u64 t; cvta.to.shared.u64 t, %1; cvt.u32.u64 %0, t; }" : "=r"(a) : "l"(p));
    return a;
}

__device__ __forceinline__ void cp16(uint32_t s, const void* g) {
    asm volatile("cp.async.cg.shared.global [%0], [%1], 16;" :: "r"(s), "l"(g));
}
#define CP_COMMIT() asm volatile("cp.async.commit_group;" ::: "memory")
#define CP_WAIT(n)  asm volatile("cp.async.wait_group %0;" :: "n"(n) : "memory")

#define LDM_X4(R, addr) \
    asm volatile("ldmatrix.sync.aligned.m8n8.x4.shared.b16 {%0,%1,%2,%3}, [%4];" \
                 : "=r"((R)[0]), "=r"((R)[1]), "=r"((R)[2]), "=r"((R)[3]) : "r"(addr))

__device__ __forceinline__ void mma_f16(float c[4], const uint32_t a[4], uint32_t b0, uint32_t b1) {
    asm volatile(
        "mma.sync.aligned.m16n8k16.row.col.f32.f16.f16.f32 "
        "{%0,%1,%2,%3}, {%4,%5,%6,%7}, {%8,%9}, {%0,%1,%2,%3};"
        : "+f"(c[0]), "+f"(c[1]), "+f"(c[2]), "+f"(c[3])
        : "r"(a[0]), "r"(a[1]), "r"(a[2]), "r"(a[3]), "r"(b0), "r"(b1));
}

// ---------------------------------------------------------------------------
// Prep kernel 1 (EXACT R15): blocks [0,128): Cayley Q = (I-S)^{-1}(I+S)
// (256 thr, 4 rows/thread, GJ no pivot). Blocks [128, 128+32768): first half
// of x -> fp16 (DRAM-bound, overlaps the latency-bound GJ).
// ---------------------------------------------------------------------------
#define XHALF 32768     // half of MROWS*IN_F / (256*4)

__global__ __launch_bounds__(256) void prep1_kernel(
    const float* __restrict__ x, const float* __restrict__ oft_r)
{
    __shared__ float A[32][33];
    __shared__ float Bm[32][33];
    int blk = blockIdx.x;
    if (blk >= NBLKS) {
        size_t i = ((size_t)(blk - NBLKS) * 256 + threadIdx.x) * 4;
        float4 v = *(const float4*)(x + i);
        *(__half2*)(g_Xh + i)     = __floats2half2_rn(v.x, v.y);
        *(__half2*)(g_Xh + i + 2) = __floats2half2_rn(v.z, v.w);
        return;
    }
    int n = blk;
    int tid = threadIdx.x;
    int j = tid & 31, i0 = tid >> 5;            // rows i0 + 8p
    const float* R = oft_r + n * 1024;
    #pragma unroll
    for (int p = 0; p < 4; p++) {
        int i = i0 + 8 * p;
        float s  = 0.5f * (R[i * 32 + j] - R[j * 32 + i]);
        float id = (i == j) ? 1.0f : 0.0f;
        A[i][j]  = id - s;
        Bm[i][j] = id + s;
    }
    __syncthreads();
    for (int k = 0; k < 32; k++) {
        float fac[4];
        #pragma unroll
        for (int p = 0; p < 4; p++) fac[p] = A[i0 + 8 * p][k] / A[k][k];
        __syncthreads();
        #pragma unroll
        for (int p = 0; p < 4; p++) {
            int i = i0 + 8 * p;
            if (i != k) {
                A[i][j]  = fmaf(-fac[p], A[k][j],  A[i][j]);
                Bm[i][j] = fmaf(-fac[p], Bm[k][j], Bm[i][j]);
            }
        }
        __syncthreads();
    }
    #pragma unroll
    for (int p = 0; p < 4; p++) {
        int i = i0 + 8 * p;
        g_Q[n * 1024 + i * 32 + j] = Bm[i][j] / A[i][i];
    }
}

// ---------------------------------------------------------------------------
// Prep kernel 2: dequant with Q ROW IN REGISTERS.
// Block = (n, 32 o's): lane loads its Q row once via 8x conflict-free
// LDS.128 (36-float padded rows -> each .128 phase hits all 32 banks), then
// 4 o-batches reuse the regs. Inner loop = pure SHFL+FMA, 4 interleaved acc
// chains. FMA order per output identical to R9/R15 -> bit-identical result.
// Blocks [DBLKS2, +32768): second half of x -> fp16 streams behind.
// ---------------------------------------------------------------------------
#define OBATCH 32
#define DBLKS2 (NBLKS * (OUT_F / OBATCH))   // 128 * 128 = 16384

__global__ __launch_bounds__(256) void prep2_kernel(
    const float* __restrict__ x, const int* __restrict__ codes,
    const float* __restrict__ codebooks, const float* __restrict__ scales)
{
    __shared__ float Qs[32][36];
    int blk = blockIdx.x;
    if (blk >= DBLKS2) {
        size_t i = ((size_t)(blk - DBLKS2 + XHALF) * 256 + threadIdx.x) * 4;
        float4 v = *(const float4*)(x + i);
        *(__half2*)(g_Xh + i)     = __floats2half2_rn(v.x, v.y);
        *(__half2*)(g_Xh + i + 2) = __floats2half2_rn(v.z, v.w);
        return;
    }
    int n = blk & 127;                       // 0..127
    int obase = (blk >> 7) * OBATCH;
    int tid = threadIdx.x;
    int w = tid >> 5, lane = tid & 31;

    for (int idx = tid; idx < 1024; idx += 256)
        Qs[idx >> 5][idx & 31] = g_Q[n * 1024 + idx];
    __syncthreads();

    // Q row of this lane -> 32 registers (8x LDS.128, conflict-free).
    float q[32];
    #pragma unroll
    for (int c = 0; c < 8; c++) {
        float4 v = *(const float4*)&Qs[lane][c * 4];
        q[4 * c] = v.x; q[4 * c + 1] = v.y; q[4 * c + 2] = v.z; q[4 * c + 3] = v.w;
    }

    // Prefetch the 4 o-batches' gathers (MLP=4 on the codes->codebook chain).
    int grp = 4 * n + (lane >> 3);
    float wvt[4], sc[4];
    int codet[4];
    #pragma unroll
    for (int t = 0; t < 4; t++)
        codet[t] = codes[(obase + 8 * t + w) * 512 + grp];
    #pragma unroll
    for (int t = 0; t < 4; t++) {
        wvt[t] = codebooks[codet[t] * 8 + (lane & 7)];
        sc[t]  = scales[obase + 8 * t + w];
    }

    float acc[4] = {0.f, 0.f, 0.f, 0.f};
    #pragma unroll
    for (int kk = 0; kk < 32; kk++) {
        #pragma unroll
        for (int t = 0; t < 4; t++) {
            float wk = __shfl_sync(0xFFFFFFFFu, wvt[t], kk);
            acc[t] = fmaf(q[kk], wk, acc[t]);
        }
    }
    #pragma unroll
    for (int t = 0; t < 4; t++) {
        int o = obase + 8 * t + w;
        g_W2h[(size_t)o * IN_F + n * 32 + lane] = __float2half_rn(acc[t] * sc[t]);
    }
}

// ---------------------------------------------------------------------------
// Kernel 3: fp16 mma.sync GEMM — EXACT R14/R15 config (proven 1319us):
// CTA 128x256, 256 threads (8 warps 2x4), warp tile 64x64, KBLK=64, 3-stage
// cp.async (144 KB), register fragment double-buffering, 128B-row j^(row&7)
// swizzle, CP_WAIT(1), fill smeared as 4x(1A+2B) across the MMA substeps.
// RF: ~225 regs x 256 thr = 58K < 64K (standing check).
// ---------------------------------------------------------------------------
#define STAGES 3
#define KBLK   64
#define TM     128
#define TN     256
#define KITERS (IN_F / KBLK)            // 64
#define A_BYTES (TM * KBLK * 2)         // 16 KB
#define B_BYTES (TN * KBLK * 2)         // 32 KB
#define STAGE_BYTES (A_BYTES + B_BYTES) // 48 KB

__device__ __forceinline__ uint32_t swz(int row, int j) {
    return (uint32_t)(row * 128 + ((j ^ (row & 7)) << 4));
}

// Quarter-fill: part p = 1 A-chunk + 2 B-chunks.
__device__ __forceinline__ void fill_part(uint32_t sb,
        const __half* gA, const __half* gB, uint32_t so0, int kb, int p)
{
    cp16(sb + so0 + p * 4096,                     gA + (size_t)p * 32 * IN_F + kb);
    cp16(sb + A_BYTES + so0 + (2 * p) * 4096,     gB + (size_t)(2 * p) * 32 * IN_F + kb);
    cp16(sb + A_BYTES + so0 + (2 * p + 1) * 4096, gB + (size_t)(2 * p + 1) * 32 * IN_F + kb);
}

__device__ __forceinline__ void stage_fill(uint32_t sb,
        const __half* gA, const __half* gB, uint32_t so0, int kb)
{
    #pragma unroll
    for (int p = 0; p < 4; p++) fill_part(sb, gA, gB, so0, kb, p);
}

__device__ __forceinline__ void frag_load(uint32_t a[4][4], uint32_t b[4][4],
                                          uint32_t sb, uint32_t aoff, uint32_t boff)
{
    #pragma unroll
    for (int mi = 0; mi < 4; mi++) LDM_X4(a[mi], sb + aoff + mi * 2048);
    #pragma unroll
    for (int p = 0; p < 4; p++)    LDM_X4(b[p], sb + A_BYTES + boff + p * 2048);
}

__device__ __forceinline__ void mma_block(float acc[4][8][4],
                                          const uint32_t a[4][4], const uint32_t b[4][4])
{
    #pragma unroll
    for (int mi = 0; mi < 4; mi++)
        #pragma unroll
        for (int p = 0; p < 4; p++) {
            mma_f16(acc[mi][2 * p],     a[mi], b[p][0], b[p][2]);
            mma_f16(acc[mi][2 * p + 1], a[mi], b[p][1], b[p][3]);
        }
}

__global__ __launch_bounds__(256, 1)
void gemm_kernel(const float* __restrict__ bias, float* __restrict__ out)
{
    extern __shared__ char smem[];
    uint32_t sbase = smem_u32(smem);
    uint32_t buf_lim = sbase + 2 * STAGE_BYTES;

    int tid  = threadIdx.x;
    int wid  = tid >> 5, lane = tid & 31;
    int g    = lane >> 2, tig = lane & 3;
    int lr   = lane & 7;
    int q    = lane >> 3;
    int wm   = (wid >> 2) * 64;
    int wn   = (wid & 3) * 64;
    int nbase = blockIdx.x * TN;
    int mbase = blockIdx.y * TM;

    int ra = wm + lr + ((q & 1) << 3);
    int rb = wn + lr + ((q & 1) << 3);
    int ja = q >> 1;
    uint32_t aoff[4], boff[4];
    #pragma unroll
    for (int s = 0; s < 4; s++) {
        aoff[s] = swz(ra, 2 * s + ja);
        boff[s] = swz(rb, 2 * s + ja);
    }

    int r0 = tid >> 3, j0 = tid & 7;
    const __half* gA = g_Xh  + (size_t)(mbase + r0) * IN_F + j0 * 8;
    const __half* gB = g_W2h + (size_t)(nbase + r0) * IN_F + j0 * 8;
    uint32_t so0 = swz(r0, j0);

    float acc[4][8][4];
    #pragma unroll
    for (int mi = 0; mi < 4; mi++)
        #pragma unroll
        for (int ni = 0; ni < 8; ni++)
            #pragma unroll
            for (int p = 0; p < 4; p++) acc[mi][ni][p] = 0.f;

    // Prologue: fill stages 0,1
    stage_fill(sbase,               gA, gB, so0, 0);
    CP_COMMIT();
    stage_fill(sbase + STAGE_BYTES, gA, gB, so0, KBLK);
    CP_COMMIT();
    CP_WAIT(1);
    __syncthreads();

    uint32_t fa[2][4][4], fb[2][4][4];
    frag_load(fa[0], fb[0], sbase, aoff[0], boff[0]);

    uint32_t sb_read = sbase;
    uint32_t sb_fill = buf_lim;

    for (int k = 0; k < KITERS; k++) {
        bool do_fill = (k + 2 < KITERS);

        #pragma unroll
        for (int s = 0; s < 4; s++) {
            if (do_fill)
                fill_part(sb_fill, gA, gB, so0, (k + 2) * KBLK, s);
            if (s < 3) {
                frag_load(fa[(s + 1) & 1], fb[(s + 1) & 1], sb_read, aoff[s + 1], boff[s + 1]);
            } else {
                CP_COMMIT();                 // single group per k-iter (after all 12)
                CP_WAIT(1);                  // stage k+1 landed
                __syncthreads();
                if (k + 1 < KITERS) {
                    uint32_t nxt = (sb_read == buf_lim) ? sbase : sb_read + STAGE_BYTES;
                    frag_load(fa[0], fb[0], nxt, aoff[0], boff[0]);
                }
            }
            mma_block(acc, fa[s & 1], fb[s & 1]);
        }

        sb_read = (sb_read == buf_lim) ? sbase : sb_read + STAGE_BYTES;
        sb_fill = (sb_fill == buf_lim) ? sbase : sb_fill + STAGE_BYTES;
    }

    // Epilogue: direct store + bias
    #pragma unroll
    for (int mi = 0; mi < 4; mi++) {
        int r = mbase + wm + mi * 16 + g;
        #pragma unroll
        for (int ni = 0; ni < 8; ni++) {
            int col = nbase + wn + ni * 8 + tig * 2;
            float2 bv = *(const float2*)(bias + col);
            float2 v0 = make_float2(acc[mi][ni][0] + bv.x, acc[mi][ni][1] + bv.y);
            float2 v1 = make_float2(acc[mi][ni][2] + bv.x, acc[mi][ni][3] + bv.y);
            *(float2*)(out + (size_t)r * OUT_F + col)       = v0;
            *(float2*)(out + (size_t)(r + 8) * OUT_F + col) = v1;
        }
    }
}

// ---------------------------------------------------------------------------
// Launch
// ---------------------------------------------------------------------------
extern "C" void kernel_launch(void* const* d_in, const int* in_sizes, int n_in,
                              void* d_out, int out_size)
{
    const float* x         = (const float*)d_in[0];
    const float* oft_r     = (const float*)d_in[1];
    const int*   codes     = (const int*)d_in[2];
    const float* codebooks = (const float*)d_in[3];
    const float* scales    = (const float*)d_in[4];
    const float* bias      = (const float*)d_in[5];
    float*       out       = (float*)d_out;

    prep1_kernel<<<NBLKS + XHALF, 256>>>(x, oft_r);
    prep2_kernel<<<DBLKS2 + XHALF, 256>>>(x, codes, codebooks, scales);

    int smem_bytes = STAGES * STAGE_BYTES;   // 144 KB
    cudaFuncSetAttribute(gemm_kernel, cudaFuncAttributeMaxDynamicSharedMemorySize, smem_bytes);
    gemm_kernel<<<dim3(OUT_F / TN, MROWS / TM), 256, smem_bytes>>>(bias, out);
}